// round 2
// baseline (speedup 1.0000x reference)
#include <cuda_runtime.h>
#include <cuda_bf16.h>
#include <math.h>

// Problem constants (fixed by the dataset)
#define NN   50000
#define EE   800000
#define DIM  128
#define HH   8
#define HID  512     // 4*DIM
#define CATD 512     // concat width

// ---------------- static scratch (allocation-free) ----------------
__device__ float g_h[(size_t)NN * DIM];          // 25.6 MB
__device__ float g_su[(size_t)NN * HH];
__device__ float g_sv[(size_t)NN * HH];
__device__ float g_ex[(size_t)EE * HH];          // 25.6 MB
__device__ float g_outdeg[NN];
__device__ int   g_count[NN];
__device__ int   g_offsets[NN + 1];
__device__ int   g_cursor[NN];
__device__ int   g_csr[EE];
__device__ float g_cat[(size_t)NN * CATD];       // 102.4 MB
__device__ float g_f[(size_t)NN * HID];          // 102.4 MB

// ---------------- zero init ----------------
__global__ void zero_kernel() {
    int i = blockIdx.x * blockDim.x + threadIdx.x;
    if (i < NN) { g_count[i] = 0; g_outdeg[i] = 0.f; }
}

// ---------------- generic tiled SIMT fp32 GEMM: C[M,Nc] = A[M,K]*B[Nc,K]^T + bias ----------------
// ACT: 0 = none, 1 = exact GELU
template <int ACT>
__global__ void __launch_bounds__(256) gemm_tn(
    const float* __restrict__ A, const float* __restrict__ B,
    const float* __restrict__ bias, float* __restrict__ C,
    int M, int K, int Nc)
{
    __shared__ float sA[16][64];
    __shared__ float sB[16][64];
    const int tid  = threadIdx.x;
    const int tx   = tid & 15;
    const int ty   = tid >> 4;
    const int bx   = blockIdx.x << 6;
    const int by   = blockIdx.y << 6;
    const int lrow = tid >> 2;        // 0..63
    const int lk   = (tid & 3) << 2;  // 0,4,8,12

    float acc[4][4];
#pragma unroll
    for (int i = 0; i < 4; i++)
#pragma unroll
        for (int j = 0; j < 4; j++) acc[i][j] = 0.f;

    const int  am     = by + lrow;
    const bool avalid = (am < M);
    const float* Aptr = A + (size_t)(avalid ? am : (M - 1)) * K + lk;
    const float* Bptr = B + (size_t)(bx + lrow) * K + lk;   // Nc always multiple of 64 here

    for (int k0 = 0; k0 < K; k0 += 16) {
        float4 av = avalid ? *(const float4*)(Aptr + k0) : make_float4(0.f, 0.f, 0.f, 0.f);
        float4 bv = *(const float4*)(Bptr + k0);
        __syncthreads();
        sA[lk + 0][lrow] = av.x; sA[lk + 1][lrow] = av.y;
        sA[lk + 2][lrow] = av.z; sA[lk + 3][lrow] = av.w;
        sB[lk + 0][lrow] = bv.x; sB[lk + 1][lrow] = bv.y;
        sB[lk + 2][lrow] = bv.z; sB[lk + 3][lrow] = bv.w;
        __syncthreads();
#pragma unroll
        for (int kk = 0; kk < 16; kk++) {
            float4 ra = *(const float4*)&sA[kk][ty << 2];
            float4 rb = *(const float4*)&sB[kk][tx << 2];
            float a4[4] = {ra.x, ra.y, ra.z, ra.w};
            float b4[4] = {rb.x, rb.y, rb.z, rb.w};
#pragma unroll
            for (int i = 0; i < 4; i++)
#pragma unroll
                for (int j = 0; j < 4; j++) acc[i][j] += a4[i] * b4[j];
        }
    }

#pragma unroll
    for (int i = 0; i < 4; i++) {
        int r = by + (ty << 2) + i;
        if (r < M) {
#pragma unroll
            for (int j = 0; j < 4; j++) {
                int c = bx + (tx << 2) + j;
                float v = acc[i][j] + bias[c];
                if (ACT == 1) v = 0.5f * v * (1.f + erff(v * 0.70710678118654752f));
                C[(size_t)r * Nc + c] = v;
            }
        }
    }
}

// ---------------- attention projections: su = h@au_w^T + au_b ; sv = h@av_w^T ----------------
__global__ void __launch_bounds__(256) attn_proj(
    const float* __restrict__ au_w, const float* __restrict__ au_b,
    const float* __restrict__ av_w)
{
    __shared__ float s_au[HH * DIM];
    __shared__ float s_av[HH * DIM];
    int t = threadIdx.x;
    for (int i = t; i < HH * DIM; i += 256) { s_au[i] = au_w[i]; s_av[i] = av_w[i]; }
    __syncthreads();

    int warp = t >> 5, lane = t & 31;
    int n = blockIdx.x * 8 + warp;
    if (n >= NN) return;

    float ua[HH], va[HH];
#pragma unroll
    for (int h = 0; h < HH; h++) { ua[h] = 0.f; va[h] = 0.f; }

    for (int d = lane; d < DIM; d += 32) {
        float hv = g_h[(size_t)n * DIM + d];
#pragma unroll
        for (int h = 0; h < HH; h++) {
            ua[h] += hv * s_au[h * DIM + d];
            va[h] += hv * s_av[h * DIM + d];
        }
    }
#pragma unroll
    for (int h = 0; h < HH; h++) {
#pragma unroll
        for (int o = 16; o > 0; o >>= 1) {
            ua[h] += __shfl_xor_sync(0xffffffffu, ua[h], o);
            va[h] += __shfl_xor_sync(0xffffffffu, va[h], o);
        }
    }
    if (lane == 0) {
#pragma unroll
        for (int h = 0; h < HH; h++) {
            g_su[(size_t)n * HH + h] = ua[h] + au_b[h];
            g_sv[(size_t)n * HH + h] = va[h];
        }
    }
}

// ---------------- edge kernel: ex = exp(leaky_relu(su[src]+sv[dst])), degree counts ----------------
__global__ void edge_kernel(const int* __restrict__ src, const int* __restrict__ dst) {
    int e = blockIdx.x * blockDim.x + threadIdx.x;
    if (e >= EE) return;
    int s = src[e], d = dst[e];
    atomicAdd(&g_count[d], 1);
    atomicAdd(&g_outdeg[s], 1.0f);

    float4 u0 = *(const float4*)(g_su + (size_t)s * 8);
    float4 u1 = *(const float4*)(g_su + (size_t)s * 8 + 4);
    float4 v0 = *(const float4*)(g_sv + (size_t)d * 8);
    float4 v1 = *(const float4*)(g_sv + (size_t)d * 8 + 4);
    float r[8] = {u0.x + v0.x, u0.y + v0.y, u0.z + v0.z, u0.w + v0.w,
                  u1.x + v1.x, u1.y + v1.y, u1.z + v1.z, u1.w + v1.w};
#pragma unroll
    for (int h = 0; h < 8; h++) {
        float x = r[h];
        x = (x > 0.f) ? x : 0.2f * x;   // LeakyReLU(0.2)
        r[h] = expf(x);                  // scores are bounded: stable without max-shift
    }
    float4* out = (float4*)(g_ex + (size_t)e * 8);
    out[0] = make_float4(r[0], r[1], r[2], r[3]);
    out[1] = make_float4(r[4], r[5], r[6], r[7]);
}

// ---------------- exclusive scan (single block, multi-tile) ----------------
__global__ void scan_kernel() {
    __shared__ int sh[1024];
    int tid = threadIdx.x;
    int run = 0;
    for (int base = 0; base < NN; base += 1024) {
        int i = base + tid;
        int v = (i < NN) ? g_count[i] : 0;
        sh[tid] = v;
        __syncthreads();
#pragma unroll
        for (int o = 1; o < 1024; o <<= 1) {
            int t2 = (tid >= o) ? sh[tid - o] : 0;
            __syncthreads();
            sh[tid] += t2;
            __syncthreads();
        }
        int incl = sh[tid];
        int total = sh[1023];
        if (i < NN) {
            g_offsets[i + 1] = run + incl;
            g_cursor[i]      = run + incl - v;   // exclusive
        }
        run += total;
        __syncthreads();
    }
    if (tid == 0) g_offsets[0] = 0;
}

// ---------------- scatter edges into CSR by dst ----------------
__global__ void scatter_kernel(const int* __restrict__ dst) {
    int e = blockIdx.x * blockDim.x + threadIdx.x;
    if (e >= EE) return;
    int pos = atomicAdd(&g_cursor[dst[e]], 1);
    g_csr[pos] = e;
}

// ---------------- per-dst-node message accumulation + cat build ----------------
// cat[n] = [ h[n] | msg[n] | sum2[n]/max(indeg,1) | msg3[n] ]
#define CHUNK 64
__global__ void __launch_bounds__(128) message_kernel(const int* __restrict__ src) {
    int n = blockIdx.x;
    int t = threadIdx.x;            // 0..127 == feature index d
    int off = g_offsets[n];
    int deg = g_offsets[n + 1] - off;

    // copy h row into cat
    float hv = g_h[(size_t)n * DIM + t];
    g_cat[(size_t)n * CATD + t] = hv;

    __shared__ float sden[8];
    __shared__ float srden[8];
    if (t < 8) sden[t] = 0.f;
    __syncthreads();

    // softmax denominator per head (CSR pass, warp-reduced)
    {
        float acc[8];
#pragma unroll
        for (int h = 0; h < 8; h++) acc[h] = 0.f;
        for (int j = t; j < deg; j += 128) {
            int e = g_csr[off + j];
            float4 a = *(const float4*)(g_ex + (size_t)e * 8);
            float4 b = *(const float4*)(g_ex + (size_t)e * 8 + 4);
            acc[0] += a.x; acc[1] += a.y; acc[2] += a.z; acc[3] += a.w;
            acc[4] += b.x; acc[5] += b.y; acc[6] += b.z; acc[7] += b.w;
        }
#pragma unroll
        for (int h = 0; h < 8; h++) {
#pragma unroll
            for (int o = 16; o > 0; o >>= 1)
                acc[h] += __shfl_xor_sync(0xffffffffu, acc[h], o);
        }
        if ((t & 31) == 0) {
#pragma unroll
            for (int h = 0; h < 8; h++) atomicAdd(&sden[h], acc[h]);
        }
    }
    __syncthreads();
    if (t < 8) srden[t] = (sden[t] > 0.f) ? (1.0f / sden[t]) : 0.f;
    __syncthreads();

    float inv_indeg = 1.0f / fmaxf((float)deg, 1.0f);
    float outdeg_n  = g_outdeg[n];

    __shared__ int   s_src[CHUNK];
    __shared__ float s_nrm[CHUNK];
    __shared__ float s_w[CHUNK * 8];

    float a1 = 0.f, a2 = 0.f, a3 = 0.f;
    for (int base = 0; base < deg; base += CHUNK) {
        int m = min(CHUNK, deg - base);
        __syncthreads();
        if (t < m) {
            int e = g_csr[off + base + t];
            int s = src[e];
            s_src[t] = s;
            s_nrm[t] = rsqrtf(g_outdeg[s] * outdeg_n);
        }
        for (int k = t; k < m * 8; k += 128) {
            int j = k >> 3, h = k & 7;
            int e = g_csr[off + base + j];
            s_w[k] = g_ex[(size_t)e * 8 + h] * srden[h];
        }
        __syncthreads();
        for (int j = 0; j < m; j++) {
            float v = g_h[(size_t)s_src[j] * DIM + t];   // coalesced 512B per edge
            a1 += v * s_w[(j << 3) + (t & 7)];
            a2 += v;
            a3 += v * s_nrm[j];
        }
    }
    size_t rowb = (size_t)n * CATD;
    g_cat[rowb + 128 + t] = a1;
    g_cat[rowb + 256 + t] = a2 * inv_indeg;
    g_cat[rowb + 384 + t] = a3;
}

// ---------------- launch ----------------
extern "C" void kernel_launch(void* const* d_in, const int* in_sizes, int n_in,
                              void* d_out, int out_size) {
    const float* x    = (const float*)d_in[0];
    const int*   src  = (const int*)  d_in[1];
    const int*   dst  = (const int*)  d_in[2];
    const float* fc_w = (const float*)d_in[3];
    const float* fc_b = (const float*)d_in[4];
    const float* au_w = (const float*)d_in[5];
    const float* au_b = (const float*)d_in[6];
    const float* av_w = (const float*)d_in[7];
    const float* w1   = (const float*)d_in[8];
    const float* b1   = (const float*)d_in[9];
    const float* w2   = (const float*)d_in[10];
    const float* b2   = (const float*)d_in[11];
    float* out = (float*)d_out;

    float* hp;  cudaGetSymbolAddress((void**)&hp,  g_h);
    float* catp; cudaGetSymbolAddress((void**)&catp, g_cat);
    float* fp;  cudaGetSymbolAddress((void**)&fp,  g_f);

    // 1. zero degree arrays
    zero_kernel<<<(NN + 255) / 256, 256>>>();

    // 2. h = x @ fc_w^T + fc_b
    {
        dim3 grid(DIM / 64, (NN + 63) / 64);
        gemm_tn<0><<<grid, 256>>>(x, fc_w, fc_b, hp, NN, DIM, DIM);
    }

    // 3. su, sv
    attn_proj<<<(NN + 7) / 8, 256>>>(au_w, au_b, av_w);

    // 4. edge exp + degrees
    edge_kernel<<<(EE + 255) / 256, 256>>>(src, dst);

    // 5. CSR offsets
    scan_kernel<<<1, 1024>>>();

    // 6. scatter into CSR
    scatter_kernel<<<(EE + 255) / 256, 256>>>(dst);

    // 7. message accumulation + cat
    message_kernel<<<NN, 128>>>(src);

    // 8. f = gelu(cat @ w1^T + b1)
    {
        dim3 grid(HID / 64, (NN + 63) / 64);
        gemm_tn<1><<<grid, 256>>>(catp, w1, b1, fp, NN, CATD, HID);
    }

    // 9. out = f @ w2^T + b2
    {
        dim3 grid(DIM / 64, (NN + 63) / 64);
        gemm_tn<0><<<grid, 256>>>(fp, w2, b2, out, NN, HID, DIM);
    }
}

// round 6
// speedup vs baseline: 1.4676x; 1.4676x over previous
#include <cuda_runtime.h>
#include <cuda_bf16.h>
#include <math.h>
#include <stdint.h>

// Problem constants (fixed by the dataset)
#define NN   50000
#define EE   800000
#define DIM  128
#define HH   8
#define HID  512     // 4*DIM
#define CATD 512     // concat width

// ---------------- static scratch (allocation-free) ----------------
__device__ float g_h[(size_t)NN * DIM];          // 25.6 MB
__device__ float g_su[(size_t)NN * HH];
__device__ float g_sv[(size_t)NN * HH];
__device__ float g_ex[(size_t)EE * HH];          // 25.6 MB
__device__ float g_outdeg[NN];
__device__ int   g_count[NN];
__device__ int   g_offsets[NN + 1];
__device__ int   g_cursor[NN];
__device__ int   g_csr[EE];
__device__ float g_cat[(size_t)NN * CATD];       // 102.4 MB
__device__ float g_f[(size_t)NN * HID];          // 102.4 MB

// =======================================================================
// helpers
// =======================================================================
__device__ __forceinline__ uint32_t smem_u32(const void* p) {
    uint32_t a;
    asm("{ .reg .u64 t; cvta.to.shared.u64 t, %1; cvt.u32.u64 %0, t; }"
        : "=r"(a) : "l"(p));
    return a;
}

__device__ __forceinline__ void ldsm4(uint32_t* r, uint32_t addr) {
    asm volatile("ldmatrix.sync.aligned.m8n8.x4.shared.b16 {%0,%1,%2,%3}, [%4];"
                 : "=r"(r[0]), "=r"(r[1]), "=r"(r[2]), "=r"(r[3]) : "r"(addr));
}

__device__ __forceinline__ void mma16816(float* c, const uint32_t* a, const uint32_t* b) {
    asm volatile(
        "mma.sync.aligned.m16n8k16.row.col.f32.bf16.bf16.f32 "
        "{%0,%1,%2,%3}, {%4,%5,%6,%7}, {%8,%9}, {%0,%1,%2,%3};"
        : "+f"(c[0]), "+f"(c[1]), "+f"(c[2]), "+f"(c[3])
        : "r"(a[0]), "r"(a[1]), "r"(a[2]), "r"(a[3]), "r"(b[0]), "r"(b[1]));
}

__device__ __forceinline__ uint32_t pk_bf2(__nv_bfloat16 a, __nv_bfloat16 b) {
    return (uint32_t)__bfloat16_as_ushort(a) | ((uint32_t)__bfloat16_as_ushort(b) << 16);
}

// fp32x4 -> bf16 hi/lo split, store 8B each to smem
__device__ __forceinline__ void st_split(__nv_bfloat16* hi, __nv_bfloat16* lo, float4 v) {
    __nv_bfloat16 h0 = __float2bfloat16(v.x);
    __nv_bfloat16 h1 = __float2bfloat16(v.y);
    __nv_bfloat16 h2 = __float2bfloat16(v.z);
    __nv_bfloat16 h3 = __float2bfloat16(v.w);
    uint2 H, L;
    H.x = pk_bf2(h0, h1); H.y = pk_bf2(h2, h3);
    L.x = pk_bf2(__float2bfloat16(v.x - __bfloat162float(h0)),
                 __float2bfloat16(v.y - __bfloat162float(h1)));
    L.y = pk_bf2(__float2bfloat16(v.z - __bfloat162float(h2)),
                 __float2bfloat16(v.w - __bfloat162float(h3)));
    *(uint2*)hi = H;
    *(uint2*)lo = L;
}

// =======================================================================
// bf16x3 mma.sync GEMM: C[M,Nc] = A[M,K] @ B[Nc,K]^T + bias, opt. GELU
// Block tile 128x128, 8 warps (2m x 4n), warp tile 64x32.
// K chunked by 32 fp32; double-buffered smem (hi/lo for A and B).
// =======================================================================
#define LDK 40   // padded row length in bf16 (32 data + 8 pad)

template <int ACT>
__global__ void __launch_bounds__(256, 1) mma_gemm(
    const float* __restrict__ A, const float* __restrict__ B,
    const float* __restrict__ bias, float* __restrict__ C,
    int M, int K, int Nc)
{
    extern __shared__ char sm[];
    // layout per stage (10240 B each): Ahi | Alo | Bhi | Blo ; 2 stages; then bias[128]
    const int STG = 4 * 128 * LDK * 2;   // 40960
    __nv_bfloat16* base = (__nv_bfloat16*)sm;
    float* s_bias = (float*)(sm + 2 * STG);

    const int tid  = threadIdx.x;
    const int wid  = tid >> 5;
    const int lane = tid & 31;
    const int m0 = blockIdx.x * 128;
    const int n0 = blockIdx.y * 128;

    if (tid < 128) s_bias[tid] = bias[n0 + tid];

    const int wm = (wid >> 2) * 64;   // warp m offset (0/64)
    const int wn = (wid & 3) * 32;    // warp n offset

    // ldmatrix per-lane offsets (same pattern for A and B)
    const int lrow = (lane & 7) + ((lane >> 3) & 1) * 8;
    const int lcol = (lane >> 4) * 8;

    float c[4][4][4];
#pragma unroll
    for (int i = 0; i < 4; i++)
#pragma unroll
        for (int j = 0; j < 4; j++)
#pragma unroll
            for (int r = 0; r < 4; r++) c[i][j][r] = 0.f;

    const int nchunks = K >> 5;   // chunks of 32 fp32

    // loader: 256 threads, each handles one (row, half) pair: 4 float4 per matrix
    const int lr  = tid >> 1;          // 0..127
    const int lhf = (tid & 1) * 16;    // 0 or 16

    auto load_chunk = [&](int ch, int s) {
        const int k0 = (ch << 5) + lhf;
        __nv_bfloat16* Ahi = base + (size_t)s * (STG / 2);
        __nv_bfloat16* Alo = Ahi + 128 * LDK;
        __nv_bfloat16* Bhi = Alo + 128 * LDK;
        __nv_bfloat16* Blo = Bhi + 128 * LDK;
        int ar = m0 + lr; if (ar >= M) ar = M - 1;   // clamp (rows unused on store)
        const float* Ap = A + (size_t)ar * K + k0;
        const float* Bp = B + (size_t)(n0 + lr) * K + k0;
        int so = lr * LDK + lhf;
#pragma unroll
        for (int j = 0; j < 4; j++) {
            float4 va = *(const float4*)(Ap + j * 4);
            st_split(Ahi + so + j * 4, Alo + so + j * 4, va);
            float4 vb = *(const float4*)(Bp + j * 4);
            st_split(Bhi + so + j * 4, Blo + so + j * 4, vb);
        }
    };

    load_chunk(0, 0);

    for (int ch = 0; ch < nchunks; ch++) {
        __syncthreads();
        if (ch + 1 < nchunks) load_chunk(ch + 1, (ch + 1) & 1);

        const int s = ch & 1;
        uint32_t sA_hi = smem_u32(base + (size_t)s * (STG / 2));
        uint32_t sA_lo = sA_hi + 128 * LDK * 2;
        uint32_t sB_hi = sA_lo + 128 * LDK * 2;
        uint32_t sB_lo = sB_hi + 128 * LDK * 2;

#pragma unroll
        for (int ks = 0; ks < 2; ks++) {
            const int kk = ks * 16;
            uint32_t ah[4][4], al[4][4], bh[4][2], bl[4][2];
#pragma unroll
            for (int mt = 0; mt < 4; mt++) {
                uint32_t off = (uint32_t)((wm + mt * 16 + lrow) * LDK + kk + lcol) * 2;
                ldsm4(ah[mt], sA_hi + off);
                ldsm4(al[mt], sA_lo + off);
            }
#pragma unroll
            for (int p = 0; p < 2; p++) {   // pairs of n-tiles
                uint32_t off = (uint32_t)((wn + p * 16 + lrow) * LDK + kk + lcol) * 2;
                uint32_t t[4];
                ldsm4(t, sB_hi + off);
                bh[2 * p][0] = t[0]; bh[2 * p + 1][0] = t[1];
                bh[2 * p][1] = t[2]; bh[2 * p + 1][1] = t[3];
                ldsm4(t, sB_lo + off);
                bl[2 * p][0] = t[0]; bl[2 * p + 1][0] = t[1];
                bl[2 * p][1] = t[2]; bl[2 * p + 1][1] = t[3];
            }
#pragma unroll
            for (int mt = 0; mt < 4; mt++)
#pragma unroll
                for (int nt = 0; nt < 4; nt++) {
                    mma16816(c[mt][nt], ah[mt], bh[nt]);
                    mma16816(c[mt][nt], ah[mt], bl[nt]);
                    mma16816(c[mt][nt], al[mt], bh[nt]);
                }
        }
    }

    // Epilogue: c[mt][nt][r]: row = m0+wm+mt*16 + lane/4 + (r>=2)*8,
    //           col = n0+wn+nt*8 + (lane%4)*2 + (r&1)
    const int er = lane >> 2;
    const int ec = (lane & 3) * 2;
#pragma unroll
    for (int mt = 0; mt < 4; mt++) {
#pragma unroll
        for (int half = 0; half < 2; half++) {
            int gm = m0 + wm + mt * 16 + er + half * 8;
            if (gm < M) {
                float* Crow = C + (size_t)gm * Nc;
#pragma unroll
                for (int nt = 0; nt < 4; nt++) {
                    int cn = wn + nt * 8 + ec;
                    float v0 = c[mt][nt][half * 2 + 0] + s_bias[cn];
                    float v1 = c[mt][nt][half * 2 + 1] + s_bias[cn + 1];
                    if (ACT == 1) {
                        v0 = 0.5f * v0 * (1.f + erff(v0 * 0.70710678118654752f));
                        v1 = 0.5f * v1 * (1.f + erff(v1 * 0.70710678118654752f));
                    }
                    float2 o; o.x = v0; o.y = v1;
                    *(float2*)(Crow + n0 + cn) = o;
                }
            }
        }
    }
}

// ---------------- zero init ----------------
__global__ void zero_kernel() {
    int i = blockIdx.x * blockDim.x + threadIdx.x;
    if (i < NN) { g_count[i] = 0; g_outdeg[i] = 0.f; }
}

// ---------------- attention projections: su = h@au_w^T + au_b ; sv = h@av_w^T ----------------
__global__ void __launch_bounds__(256) attn_proj(
    const float* __restrict__ au_w, const float* __restrict__ au_b,
    const float* __restrict__ av_w)
{
    __shared__ float s_au[HH * DIM];
    __shared__ float s_av[HH * DIM];
    int t = threadIdx.x;
    for (int i = t; i < HH * DIM; i += 256) { s_au[i] = au_w[i]; s_av[i] = av_w[i]; }
    __syncthreads();

    int warp = t >> 5, lane = t & 31;
    int n = blockIdx.x * 8 + warp;
    if (n >= NN) return;

    float ua[HH], va[HH];
#pragma unroll
    for (int h = 0; h < HH; h++) { ua[h] = 0.f; va[h] = 0.f; }

    for (int d = lane; d < DIM; d += 32) {
        float hv = g_h[(size_t)n * DIM + d];
#pragma unroll
        for (int h = 0; h < HH; h++) {
            ua[h] += hv * s_au[h * DIM + d];
            va[h] += hv * s_av[h * DIM + d];
        }
    }
#pragma unroll
    for (int h = 0; h < HH; h++) {
#pragma unroll
        for (int o = 16; o > 0; o >>= 1) {
            ua[h] += __shfl_xor_sync(0xffffffffu, ua[h], o);
            va[h] += __shfl_xor_sync(0xffffffffu, va[h], o);
        }
    }
    if (lane == 0) {
#pragma unroll
        for (int h = 0; h < HH; h++) {
            g_su[(size_t)n * HH + h] = ua[h] + au_b[h];
            g_sv[(size_t)n * HH + h] = va[h];
        }
    }
}

// ---------------- edge kernel ----------------
__global__ void edge_kernel(const int* __restrict__ src, const int* __restrict__ dst) {
    int e = blockIdx.x * blockDim.x + threadIdx.x;
    if (e >= EE) return;
    int s = src[e], d = dst[e];
    atomicAdd(&g_count[d], 1);
    atomicAdd(&g_outdeg[s], 1.0f);

    float4 u0 = *(const float4*)(g_su + (size_t)s * 8);
    float4 u1 = *(const float4*)(g_su + (size_t)s * 8 + 4);
    float4 v0 = *(const float4*)(g_sv + (size_t)d * 8);
    float4 v1 = *(const float4*)(g_sv + (size_t)d * 8 + 4);
    float r[8] = {u0.x + v0.x, u0.y + v0.y, u0.z + v0.z, u0.w + v0.w,
                  u1.x + v1.x, u1.y + v1.y, u1.z + v1.z, u1.w + v1.w};
#pragma unroll
    for (int h = 0; h < 8; h++) {
        float x = r[h];
        x = (x > 0.f) ? x : 0.2f * x;   // LeakyReLU(0.2)
        r[h] = expf(x);                  // scores bounded: stable without max-shift
    }
    float4* out = (float4*)(g_ex + (size_t)e * 8);
    out[0] = make_float4(r[0], r[1], r[2], r[3]);
    out[1] = make_float4(r[4], r[5], r[6], r[7]);
}

// ---------------- exclusive scan (single block, multi-tile) ----------------
__global__ void scan_kernel() {
    __shared__ int sh[1024];
    int tid = threadIdx.x;
    int run = 0;
    for (int base = 0; base < NN; base += 1024) {
        int i = base + tid;
        int v = (i < NN) ? g_count[i] : 0;
        sh[tid] = v;
        __syncthreads();
#pragma unroll
        for (int o = 1; o < 1024; o <<= 1) {
            int t2 = (tid >= o) ? sh[tid - o] : 0;
            __syncthreads();
            sh[tid] += t2;
            __syncthreads();
        }
        int incl = sh[tid];
        int total = sh[1023];
        if (i < NN) {
            g_offsets[i + 1] = run + incl;
            g_cursor[i]      = run + incl - v;   // exclusive
        }
        run += total;
        __syncthreads();
    }
    if (tid == 0) g_offsets[0] = 0;
}

// ---------------- scatter edges into CSR by dst ----------------
__global__ void scatter_kernel(const int* __restrict__ dst) {
    int e = blockIdx.x * blockDim.x + threadIdx.x;
    if (e >= EE) return;
    int pos = atomicAdd(&g_cursor[dst[e]], 1);
    g_csr[pos] = e;
}

// ---------------- per-dst-node message accumulation + cat build ----------------
#define CHUNK 64
__global__ void __launch_bounds__(128) message_kernel(const int* __restrict__ src) {
    int n = blockIdx.x;
    int t = threadIdx.x;            // 0..127 == feature index d
    int off = g_offsets[n];
    int deg = g_offsets[n + 1] - off;

    float hv = g_h[(size_t)n * DIM + t];
    g_cat[(size_t)n * CATD + t] = hv;

    __shared__ float sden[8];
    __shared__ float srden[8];
    if (t < 8) sden[t] = 0.f;
    __syncthreads();

    {
        float acc[8];
#pragma unroll
        for (int h = 0; h < 8; h++) acc[h] = 0.f;
        for (int j = t; j < deg; j += 128) {
            int e = g_csr[off + j];
            float4 a = *(const float4*)(g_ex + (size_t)e * 8);
            float4 b = *(const float4*)(g_ex + (size_t)e * 8 + 4);
            acc[0] += a.x; acc[1] += a.y; acc[2] += a.z; acc[3] += a.w;
            acc[4] += b.x; acc[5] += b.y; acc[6] += b.z; acc[7] += b.w;
        }
#pragma unroll
        for (int h = 0; h < 8; h++) {
#pragma unroll
            for (int o = 16; o > 0; o >>= 1)
                acc[h] += __shfl_xor_sync(0xffffffffu, acc[h], o);
        }
        if ((t & 31) == 0) {
#pragma unroll
            for (int h = 0; h < 8; h++) atomicAdd(&sden[h], acc[h]);
        }
    }
    __syncthreads();
    if (t < 8) srden[t] = (sden[t] > 0.f) ? (1.0f / sden[t]) : 0.f;
    __syncthreads();

    float inv_indeg = 1.0f / fmaxf((float)deg, 1.0f);
    float outdeg_n  = g_outdeg[n];

    __shared__ int   s_src[CHUNK];
    __shared__ float s_nrm[CHUNK];
    __shared__ float s_w[CHUNK * 8];

    float a1 = 0.f, a2 = 0.f, a3 = 0.f;
    for (int base = 0; base < deg; base += CHUNK) {
        int m = min(CHUNK, deg - base);
        __syncthreads();
        if (t < m) {
            int e = g_csr[off + base + t];
            int s = src[e];
            s_src[t] = s;
            s_nrm[t] = rsqrtf(g_outdeg[s] * outdeg_n);
        }
        for (int k = t; k < m * 8; k += 128) {
            int j = k >> 3, h = k & 7;
            int e = g_csr[off + base + j];
            s_w[k] = g_ex[(size_t)e * 8 + h] * srden[h];
        }
        __syncthreads();
        for (int j = 0; j < m; j++) {
            float v = g_h[(size_t)s_src[j] * DIM + t];
            a1 += v * s_w[(j << 3) + (t & 7)];
            a2 += v;
            a3 += v * s_nrm[j];
        }
    }
    size_t rowb = (size_t)n * CATD;
    g_cat[rowb + 128 + t] = a1;
    g_cat[rowb + 256 + t] = a2 * inv_indeg;
    g_cat[rowb + 384 + t] = a3;
}

// ---------------- launch ----------------
extern "C" void kernel_launch(void* const* d_in, const int* in_sizes, int n_in,
                              void* d_out, int out_size) {
    const float* x    = (const float*)d_in[0];
    const int*   src  = (const int*)  d_in[1];
    const int*   dst  = (const int*)  d_in[2];
    const float* fc_w = (const float*)d_in[3];
    const float* fc_b = (const float*)d_in[4];
    const float* au_w = (const float*)d_in[5];
    const float* au_b = (const float*)d_in[6];
    const float* av_w = (const float*)d_in[7];
    const float* w1   = (const float*)d_in[8];
    const float* b1   = (const float*)d_in[9];
    const float* w2   = (const float*)d_in[10];
    const float* b2   = (const float*)d_in[11];
    float* out = (float*)d_out;

    float* hp;   cudaGetSymbolAddress((void**)&hp,  g_h);
    float* catp; cudaGetSymbolAddress((void**)&catp, g_cat);
    float* fp;   cudaGetSymbolAddress((void**)&fp,  g_f);

    const int SMEM = 2 * (4 * 128 * LDK * 2) + 512;   // 82432 bytes
    cudaFuncSetAttribute(mma_gemm<0>, cudaFuncAttributeMaxDynamicSharedMemorySize, SMEM);
    cudaFuncSetAttribute(mma_gemm<1>, cudaFuncAttributeMaxDynamicSharedMemorySize, SMEM);

    const int MT = (NN + 127) / 128;  // 391

    // 1. zero degree arrays
    zero_kernel<<<(NN + 255) / 256, 256>>>();

    // 2. h = x @ fc_w^T + fc_b
    mma_gemm<0><<<dim3(MT, 1), 256, SMEM>>>(x, fc_w, fc_b, hp, NN, DIM, DIM);

    // 3. su, sv
    attn_proj<<<(NN + 7) / 8, 256>>>(au_w, au_b, av_w);

    // 4. edge exp + degrees
    edge_kernel<<<(EE + 255) / 256, 256>>>(src, dst);

    // 5. CSR offsets
    scan_kernel<<<1, 1024>>>();

    // 6. scatter into CSR
    scatter_kernel<<<(EE + 255) / 256, 256>>>(dst);

    // 7. message accumulation + cat
    message_kernel<<<NN, 128>>>(src);

    // 8. f = gelu(cat @ w1^T + b1)
    mma_gemm<1><<<dim3(MT, 4), 256, SMEM>>>(catp, w1, b1, fp, NN, CATD, HID);

    // 9. out = f @ w2^T + b2
    mma_gemm<0><<<dim3(MT, 1), 256, SMEM>>>(fp, w2, b2, out, NN, HID, DIM);
}

// round 7
// speedup vs baseline: 2.0631x; 1.4057x over previous
#include <cuda_runtime.h>
#include <cuda_bf16.h>
#include <math.h>
#include <stdint.h>

#define NN   50000
#define EE   800000
#define DIM  128
#define HH   8
#define HID  512
#define CATD 512

typedef __nv_bfloat16 bf16;

// ---------------- static scratch ----------------
__device__ float g_h[(size_t)NN * DIM];
__device__ float g_su[(size_t)NN * HH];
__device__ float g_sv[(size_t)NN * HH];
__device__ float g_ex[(size_t)EE * HH];
__device__ float g_outdeg[NN];
__device__ int   g_count[NN];
__device__ int   g_offsets[NN + 1];
__device__ int   g_cursor[NN];
__device__ int   g_csr[EE];
__device__ int   g_bsum[64];

// bf16 hi/lo operand storage
__device__ bf16 g_x16h[(size_t)NN * DIM],  g_x16l[(size_t)NN * DIM];
__device__ bf16 g_cath[(size_t)NN * CATD], g_catl[(size_t)NN * CATD];
__device__ bf16 g_fh[(size_t)NN * HID],    g_fl[(size_t)NN * HID];
__device__ bf16 g_fcwh[DIM * DIM],  g_fcwl[DIM * DIM];
__device__ bf16 g_w1h[HID * CATD],  g_w1l[HID * CATD];
__device__ bf16 g_w2h[DIM * HID],   g_w2l[DIM * HID];

// ---------------- helpers ----------------
__device__ __forceinline__ uint32_t smem_u32(const void* p) {
    uint32_t a;
    asm("{ .reg .u64 t; cvta.to.shared.u64 t, %1; cvt.u32.u64 %0, t; }"
        : "=r"(a) : "l"(p));
    return a;
}
__device__ __forceinline__ void ldsm4(uint32_t* r, uint32_t addr) {
    asm volatile("ldmatrix.sync.aligned.m8n8.x4.shared.b16 {%0,%1,%2,%3}, [%4];"
                 : "=r"(r[0]), "=r"(r[1]), "=r"(r[2]), "=r"(r[3]) : "r"(addr));
}
__device__ __forceinline__ void mma16816(float* c, const uint32_t* a, const uint32_t* b) {
    asm volatile(
        "mma.sync.aligned.m16n8k16.row.col.f32.bf16.bf16.f32 "
        "{%0,%1,%2,%3}, {%4,%5,%6,%7}, {%8,%9}, {%0,%1,%2,%3};"
        : "+f"(c[0]), "+f"(c[1]), "+f"(c[2]), "+f"(c[3])
        : "r"(a[0]), "r"(a[1]), "r"(a[2]), "r"(a[3]), "r"(b[0]), "r"(b[1]));
}
__device__ __forceinline__ uint32_t pk_bf2(bf16 a, bf16 b) {
    return (uint32_t)__bfloat16_as_ushort(a) | ((uint32_t)__bfloat16_as_ushort(b) << 16);
}
__device__ __forceinline__ void cpa16(uint32_t dst, const void* src) {
    asm volatile("cp.async.ca.shared.global [%0], [%1], 16;" :: "r"(dst), "l"(src));
}
__device__ __forceinline__ void w16(bf16* hp, bf16* lp, float v) {
    bf16 h = __float2bfloat16(v);
    *hp = h;
    *lp = __float2bfloat16(v - __bfloat162float(h));
}

// ---------------- fp32 -> bf16 hi/lo split ----------------
__global__ void split_kernel(const float* __restrict__ in,
                             bf16* __restrict__ hi, bf16* __restrict__ lo, int n) {
    int i = (blockIdx.x * blockDim.x + threadIdx.x) * 4;
    if (i >= n) return;
    float4 v = *(const float4*)(in + i);
    bf16 h0 = __float2bfloat16(v.x), h1 = __float2bfloat16(v.y);
    bf16 h2 = __float2bfloat16(v.z), h3 = __float2bfloat16(v.w);
    uint2 H, L;
    H.x = pk_bf2(h0, h1); H.y = pk_bf2(h2, h3);
    L.x = pk_bf2(__float2bfloat16(v.x - __bfloat162float(h0)),
                 __float2bfloat16(v.y - __bfloat162float(h1)));
    L.y = pk_bf2(__float2bfloat16(v.z - __bfloat162float(h2)),
                 __float2bfloat16(v.w - __bfloat162float(h3)));
    *(uint2*)(hi + i) = H;
    *(uint2*)(lo + i) = L;
}

// =======================================================================
// bf16x3 mma.sync GEMM, pre-split bf16 hi/lo inputs loaded via cp.async.
// Block tile 128x128, 8 warps (2m x 4n), warp tile 64x32, K-chunk 32.
// 3-stage cp.async pipeline. OUTMODE: 0=f32 C, 1=bf16 hi/lo, 2=both.
// =======================================================================
#define LDK  40        // elements per smem row (32 data + 8 pad)
#define ROWB 80        // bytes per smem row
#define ARRB (128 * ROWB)
#define STGB (4 * ARRB)

template <int ACT, int OUTMODE>
__global__ void __launch_bounds__(256, 1) mma_gemm16(
    const bf16* __restrict__ Ahi, const bf16* __restrict__ Alo,
    const bf16* __restrict__ Bhi, const bf16* __restrict__ Blo,
    const float* __restrict__ bias,
    float* __restrict__ C, int ldc,
    bf16* __restrict__ Chi, bf16* __restrict__ Clo, int ldc16,
    int M, int K, int Nc)
{
    extern __shared__ char sm[];
    float* s_bias = (float*)(sm + 3 * STGB);

    const int tid  = threadIdx.x;
    const int wid  = tid >> 5;
    const int lane = tid & 31;
    const int m0 = blockIdx.x * 128;
    const int n0 = blockIdx.y * 128;
    const uint32_t sbase = smem_u32(sm);

    if (tid < 128) s_bias[tid] = bias[n0 + tid];

    const int wm = (wid >> 2) * 64;
    const int wn = (wid & 3) * 32;
    const int lrow = (lane & 7) + ((lane >> 3) & 1) * 8;
    const int lcol = (lane >> 4) * 8;

    float c[4][4][4];
#pragma unroll
    for (int i = 0; i < 4; i++)
#pragma unroll
        for (int j = 0; j < 4; j++)
#pragma unroll
            for (int r = 0; r < 4; r++) c[i][j][r] = 0.f;

    const int nchunks = K >> 5;

    const char* srcs[4] = {(const char*)Ahi, (const char*)Alo,
                           (const char*)Bhi, (const char*)Blo};

    auto load_chunk = [&](int ch, int s) {
        const int k0b = ch * 64;   // 32 bf16 = 64 bytes
#pragma unroll
        for (int t = 0; t < 8; t++) {
            int idx  = tid + t * 256;
            int unit = idx & 3;
            int row  = (idx >> 2) & 127;
            int arr  = idx >> 9;
            int grow = (arr < 2) ? min(m0 + row, M - 1) : (n0 + row);
            const char* src = srcs[arr] + (size_t)grow * (K * 2) + k0b + unit * 16;
            uint32_t dst = sbase + s * STGB + arr * ARRB + row * ROWB + unit * 16;
            cpa16(dst, src);
        }
        asm volatile("cp.async.commit_group;" ::: "memory");
    };

    load_chunk(0, 0);
    if (nchunks > 1) load_chunk(1, 1);

    for (int ch = 0; ch < nchunks; ch++) {
        if (ch + 1 < nchunks) {
            asm volatile("cp.async.wait_group 1;" ::: "memory");
        } else {
            asm volatile("cp.async.wait_group 0;" ::: "memory");
        }
        __syncthreads();
        if (ch + 2 < nchunks) load_chunk(ch + 2, (ch + 2) % 3);

        const int s = ch % 3;
        uint32_t sA_hi = sbase + s * STGB;
        uint32_t sA_lo = sA_hi + ARRB;
        uint32_t sB_hi = sA_lo + ARRB;
        uint32_t sB_lo = sB_hi + ARRB;

#pragma unroll
        for (int ks = 0; ks < 2; ks++) {
            const int kk = ks * 16;
            uint32_t ah[4][4], al[4][4], bh[4][2], bl[4][2];
#pragma unroll
            for (int mt = 0; mt < 4; mt++) {
                uint32_t off = (uint32_t)((wm + mt * 16 + lrow) * LDK + kk + lcol) * 2;
                ldsm4(ah[mt], sA_hi + off);
                ldsm4(al[mt], sA_lo + off);
            }
#pragma unroll
            for (int p = 0; p < 2; p++) {
                uint32_t off = (uint32_t)((wn + p * 16 + lrow) * LDK + kk + lcol) * 2;
                uint32_t t[4];
                ldsm4(t, sB_hi + off);
                bh[2 * p][0] = t[0]; bh[2 * p + 1][0] = t[1];
                bh[2 * p][1] = t[2]; bh[2 * p + 1][1] = t[3];
                ldsm4(t, sB_lo + off);
                bl[2 * p][0] = t[0]; bl[2 * p + 1][0] = t[1];
                bl[2 * p][1] = t[2]; bl[2 * p + 1][1] = t[3];
            }
#pragma unroll
            for (int mt = 0; mt < 4; mt++)
#pragma unroll
                for (int nt = 0; nt < 4; nt++) {
                    mma16816(c[mt][nt], ah[mt], bh[nt]);
                    mma16816(c[mt][nt], ah[mt], bl[nt]);
                    mma16816(c[mt][nt], al[mt], bh[nt]);
                }
        }
    }

    const int er = lane >> 2;
    const int ec = (lane & 3) * 2;
#pragma unroll
    for (int mt = 0; mt < 4; mt++) {
#pragma unroll
        for (int half = 0; half < 2; half++) {
            int gm = m0 + wm + mt * 16 + er + half * 8;
            if (gm < M) {
#pragma unroll
                for (int nt = 0; nt < 4; nt++) {
                    int cn = wn + nt * 8 + ec;
                    float v0 = c[mt][nt][half * 2 + 0] + s_bias[cn];
                    float v1 = c[mt][nt][half * 2 + 1] + s_bias[cn + 1];
                    if (ACT == 1) {
                        v0 = 0.5f * v0 * (1.f + erff(v0 * 0.70710678118654752f));
                        v1 = 0.5f * v1 * (1.f + erff(v1 * 0.70710678118654752f));
                    }
                    if (OUTMODE != 1) {
                        float2 o; o.x = v0; o.y = v1;
                        *(float2*)(C + (size_t)gm * ldc + n0 + cn) = o;
                    }
                    if (OUTMODE >= 1) {
                        bf16 h0 = __float2bfloat16(v0);
                        bf16 h1 = __float2bfloat16(v1);
                        uint32_t H = pk_bf2(h0, h1);
                        uint32_t L = pk_bf2(__float2bfloat16(v0 - __bfloat162float(h0)),
                                            __float2bfloat16(v1 - __bfloat162float(h1)));
                        size_t o16 = (size_t)gm * ldc16 + n0 + cn;
                        *(uint32_t*)(Chi + o16) = H;
                        *(uint32_t*)(Clo + o16) = L;
                    }
                }
            }
        }
    }
}

// ---------------- zero init ----------------
__global__ void zero_kernel() {
    int i = blockIdx.x * blockDim.x + threadIdx.x;
    if (i < NN) { g_count[i] = 0; g_outdeg[i] = 0.f; }
}

// ---------------- attention projections ----------------
__global__ void __launch_bounds__(256) attn_proj(
    const float* __restrict__ au_w, const float* __restrict__ au_b,
    const float* __restrict__ av_w)
{
    __shared__ float s_au[HH * DIM];
    __shared__ float s_av[HH * DIM];
    int t = threadIdx.x;
    for (int i = t; i < HH * DIM; i += 256) { s_au[i] = au_w[i]; s_av[i] = av_w[i]; }
    __syncthreads();

    int warp = t >> 5, lane = t & 31;
    int n = blockIdx.x * 8 + warp;
    if (n >= NN) return;

    float ua[HH], va[HH];
#pragma unroll
    for (int h = 0; h < HH; h++) { ua[h] = 0.f; va[h] = 0.f; }

    for (int d = lane; d < DIM; d += 32) {
        float hv = g_h[(size_t)n * DIM + d];
#pragma unroll
        for (int h = 0; h < HH; h++) {
            ua[h] += hv * s_au[h * DIM + d];
            va[h] += hv * s_av[h * DIM + d];
        }
    }
#pragma unroll
    for (int h = 0; h < HH; h++) {
#pragma unroll
        for (int o = 16; o > 0; o >>= 1) {
            ua[h] += __shfl_xor_sync(0xffffffffu, ua[h], o);
            va[h] += __shfl_xor_sync(0xffffffffu, va[h], o);
        }
    }
    if (lane == 0) {
#pragma unroll
        for (int h = 0; h < HH; h++) {
            g_su[(size_t)n * HH + h] = ua[h] + au_b[h];
            g_sv[(size_t)n * HH + h] = va[h];
        }
    }
}

// ---------------- edge kernel ----------------
__global__ void edge_kernel(const int* __restrict__ src, const int* __restrict__ dst) {
    int e = blockIdx.x * blockDim.x + threadIdx.x;
    if (e >= EE) return;
    int s = src[e], d = dst[e];
    atomicAdd(&g_count[d], 1);
    atomicAdd(&g_outdeg[s], 1.0f);

    float4 u0 = *(const float4*)(g_su + (size_t)s * 8);
    float4 u1 = *(const float4*)(g_su + (size_t)s * 8 + 4);
    float4 v0 = *(const float4*)(g_sv + (size_t)d * 8);
    float4 v1 = *(const float4*)(g_sv + (size_t)d * 8 + 4);
    float r[8] = {u0.x + v0.x, u0.y + v0.y, u0.z + v0.z, u0.w + v0.w,
                  u1.x + v1.x, u1.y + v1.y, u1.z + v1.z, u1.w + v1.w};
#pragma unroll
    for (int h = 0; h < 8; h++) {
        float x = r[h];
        x = (x > 0.f) ? x : 0.2f * x;
        r[h] = expf(x);
    }
    float4* out = (float4*)(g_ex + (size_t)e * 8);
    out[0] = make_float4(r[0], r[1], r[2], r[3]);
    out[1] = make_float4(r[4], r[5], r[6], r[7]);
}

// ---------------- parallel scan (3 kernels) ----------------
__global__ void scan_a() {
    __shared__ int sh[1024];
    int tid = threadIdx.x;
    int i = blockIdx.x * 1024 + tid;
    int v = (i < NN) ? g_count[i] : 0;
    sh[tid] = v;
    __syncthreads();
#pragma unroll
    for (int o = 1; o < 1024; o <<= 1) {
        int t2 = (tid >= o) ? sh[tid - o] : 0;
        __syncthreads();
        sh[tid] += t2;
        __syncthreads();
    }
    if (i < NN) g_offsets[i + 1] = sh[tid];   // tile-local inclusive (temp)
    if (tid == 1023) g_bsum[blockIdx.x] = sh[1023];
}
__global__ void scan_b(int ntiles) {
    if (threadIdx.x == 0) {
        int run = 0;
        for (int i = 0; i < ntiles; i++) { int t = g_bsum[i]; g_bsum[i] = run; run += t; }
    }
}
__global__ void scan_c() {
    int i = blockIdx.x * 1024 + threadIdx.x;
    if (i >= NN) return;
    int base = g_bsum[i >> 10];
    int incl = g_offsets[i + 1];
    int v = g_count[i];
    g_offsets[i + 1] = base + incl;
    g_cursor[i] = base + incl - v;
    if (i == 0) g_offsets[0] = 0;
}

// ---------------- scatter edges into CSR by dst ----------------
__global__ void scatter_kernel(const int* __restrict__ dst) {
    int e = blockIdx.x * blockDim.x + threadIdx.x;
    if (e >= EE) return;
    int pos = atomicAdd(&g_cursor[dst[e]], 1);
    g_csr[pos] = e;
}

// ---------------- message accumulation + cat(hi/lo) build ----------------
#define CHUNK 64
__global__ void __launch_bounds__(128) message_kernel(const int* __restrict__ src) {
    int n = blockIdx.x;
    int t = threadIdx.x;
    int off = g_offsets[n];
    int deg = g_offsets[n + 1] - off;

    __shared__ float sden[8];
    __shared__ float srden[8];
    if (t < 8) sden[t] = 0.f;
    __syncthreads();

    {
        float acc[8];
#pragma unroll
        for (int h = 0; h < 8; h++) acc[h] = 0.f;
        for (int j = t; j < deg; j += 128) {
            int e = g_csr[off + j];
            float4 a = *(const float4*)(g_ex + (size_t)e * 8);
            float4 b = *(const float4*)(g_ex + (size_t)e * 8 + 4);
            acc[0] += a.x; acc[1] += a.y; acc[2] += a.z; acc[3] += a.w;
            acc[4] += b.x; acc[5] += b.y; acc[6] += b.z; acc[7] += b.w;
        }
#pragma unroll
        for (int h = 0; h < 8; h++) {
#pragma unroll
            for (int o = 16; o > 0; o >>= 1)
                acc[h] += __shfl_xor_sync(0xffffffffu, acc[h], o);
        }
        if ((t & 31) == 0) {
#pragma unroll
            for (int h = 0; h < 8; h++) atomicAdd(&sden[h], acc[h]);
        }
    }
    __syncthreads();
    if (t < 8) srden[t] = (sden[t] > 0.f) ? (1.0f / sden[t]) : 0.f;
    __syncthreads();

    float inv_indeg = 1.0f / fmaxf((float)deg, 1.0f);
    float outdeg_n  = g_outdeg[n];

    __shared__ int   s_src[CHUNK];
    __shared__ float s_nrm[CHUNK];
    __shared__ float s_w[CHUNK * 8];

    float a1 = 0.f, a2 = 0.f, a3 = 0.f;
    for (int base = 0; base < deg; base += CHUNK) {
        int m = min(CHUNK, deg - base);
        __syncthreads();
        if (t < m) {
            int e = g_csr[off + base + t];
            int s = src[e];
            s_src[t] = s;
            s_nrm[t] = rsqrtf(g_outdeg[s] * outdeg_n);
        }
        for (int k = t; k < m * 8; k += 128) {
            int j = k >> 3, h = k & 7;
            int e = g_csr[off + base + j];
            s_w[k] = g_ex[(size_t)e * 8 + h] * srden[h];
        }
        __syncthreads();
        for (int j = 0; j < m; j++) {
            float v = g_h[(size_t)s_src[j] * DIM + t];
            a1 += v * s_w[(j << 3) + (t & 7)];
            a2 += v;
            a3 += v * s_nrm[j];
        }
    }
    size_t rowb = (size_t)n * CATD;
    w16(g_cath + rowb + 128 + t, g_catl + rowb + 128 + t, a1);
    w16(g_cath + rowb + 256 + t, g_catl + rowb + 256 + t, a2 * inv_indeg);
    w16(g_cath + rowb + 384 + t, g_catl + rowb + 384 + t, a3);
}

// ---------------- launch ----------------
extern "C" void kernel_launch(void* const* d_in, const int* in_sizes, int n_in,
                              void* d_out, int out_size) {
    const float* x    = (const float*)d_in[0];
    const int*   src  = (const int*)  d_in[1];
    const int*   dst  = (const int*)  d_in[2];
    const float* fc_w = (const float*)d_in[3];
    const float* fc_b = (const float*)d_in[4];
    const float* au_w = (const float*)d_in[5];
    const float* au_b = (const float*)d_in[6];
    const float* av_w = (const float*)d_in[7];
    const float* w1   = (const float*)d_in[8];
    const float* b1   = (const float*)d_in[9];
    const float* w2   = (const float*)d_in[10];
    const float* b2   = (const float*)d_in[11];
    float* out = (float*)d_out;

    float* hp;  cudaGetSymbolAddress((void**)&hp, g_h);
    bf16 *x16h, *x16l, *cath, *catl, *fh, *fl, *fcwh, *fcwl, *w1h, *w1l, *w2h, *w2l;
    cudaGetSymbolAddress((void**)&x16h, g_x16h); cudaGetSymbolAddress((void**)&x16l, g_x16l);
    cudaGetSymbolAddress((void**)&cath, g_cath); cudaGetSymbolAddress((void**)&catl, g_catl);
    cudaGetSymbolAddress((void**)&fh,   g_fh);   cudaGetSymbolAddress((void**)&fl,   g_fl);
    cudaGetSymbolAddress((void**)&fcwh, g_fcwh); cudaGetSymbolAddress((void**)&fcwl, g_fcwl);
    cudaGetSymbolAddress((void**)&w1h,  g_w1h);  cudaGetSymbolAddress((void**)&w1l,  g_w1l);
    cudaGetSymbolAddress((void**)&w2h,  g_w2h);  cudaGetSymbolAddress((void**)&w2l,  g_w2l);

    const int SMEM = 3 * STGB + 512;   // 123392
    cudaFuncSetAttribute(mma_gemm16<0, 2>, cudaFuncAttributeMaxDynamicSharedMemorySize, SMEM);
    cudaFuncSetAttribute(mma_gemm16<1, 1>, cudaFuncAttributeMaxDynamicSharedMemorySize, SMEM);
    cudaFuncSetAttribute(mma_gemm16<0, 0>, cudaFuncAttributeMaxDynamicSharedMemorySize, SMEM);

    const int MT = (NN + 127) / 128;   // 391
    const int NT = (NN + 1023) / 1024; // 49

    // 1. zero + weight/input splits
    zero_kernel<<<(NN + 255) / 256, 256>>>();
    split_kernel<<<(NN * DIM / 4 + 255) / 256, 256>>>(x, x16h, x16l, NN * DIM);
    split_kernel<<<(DIM * DIM / 4 + 255) / 256, 256>>>(fc_w, fcwh, fcwl, DIM * DIM);
    split_kernel<<<(HID * CATD / 4 + 255) / 256, 256>>>(w1, w1h, w1l, HID * CATD);
    split_kernel<<<(DIM * HID / 4 + 255) / 256, 256>>>(w2, w2h, w2l, DIM * HID);

    // 2. h = x @ fc_w^T + fc_b  -> g_h fp32 + cat[:,0:128] hi/lo
    mma_gemm16<0, 2><<<dim3(MT, 1), 256, SMEM>>>(
        x16h, x16l, fcwh, fcwl, fc_b, hp, DIM, cath, catl, CATD, NN, DIM, DIM);

    // 3. su, sv
    attn_proj<<<(NN + 7) / 8, 256>>>(au_w, au_b, av_w);

    // 4. edge exp + degrees
    edge_kernel<<<(EE + 255) / 256, 256>>>(src, dst);

    // 5. CSR offsets (parallel scan)
    scan_a<<<NT, 1024>>>();
    scan_b<<<1, 32>>>(NT);
    scan_c<<<NT, 1024>>>();

    // 6. scatter into CSR
    scatter_kernel<<<(EE + 255) / 256, 256>>>(dst);

    // 7. message accumulation + cat hi/lo
    message_kernel<<<NN, 128>>>(src);

    // 8. f = gelu(cat @ w1^T + b1) -> f hi/lo
    mma_gemm16<1, 1><<<dim3(MT, 4), 256, SMEM>>>(
        cath, catl, w1h, w1l, b1, nullptr, 0, fh, fl, HID, NN, CATD, HID);

    // 9. out = f @ w2^T + b2
    mma_gemm16<0, 0><<<dim3(MT, 1), 256, SMEM>>>(
        fh, fl, w2h, w2l, b2, out, DIM, nullptr, nullptr, 0, NN, HID, DIM);
}